// round 4
// baseline (speedup 1.0000x reference)
#include <cuda_runtime.h>
#include <cuda_bf16.h>

#define IMG_H 4096
#define IMG_W 4096
#define OUT_H 4097
#define OUT_W 4097
#define TILE  32
#define HIST  35   // TILE + 3
#define INW   37   // HIST + 2 (sobel halo)
#define INP   38   // padded input row stride (words)
#define HP    37   // packed (mag|idx) row stride -- odd => conflict-free strided reads
#define RSP   33   // s_rs row stride in float4 units

// cos(pi/8), sin(pi/8)
#define CC 0.92387953251128674f
#define SS 0.38268343236508978f

__device__ __forceinline__ float4 f4add(float4 a, float4 b) {
    return make_float4(a.x + b.x, a.y + b.y, a.z + b.z, a.w + b.w);
}
__device__ __forceinline__ float4 f4addsub(float4 a, float4 p, float4 m) {
    return make_float4(a.x + p.x - m.x, a.y + p.y - m.y,
                       a.z + p.z - m.z, a.w + p.w - m.w);
}

__global__ __launch_bounds__(256, 5)
void sift_fused_kernel(const float* __restrict__ x, float* __restrict__ out)
{
    // rs: [chan-group][hist row][x], row stride 33 float4
    __shared__ float4       s_rs[2][HIST][RSP];   // 36960 B (aliased as input tile)
    __shared__ unsigned int s_pk[HIST][HP];       //  5180 B  packed mag|idx
    // total 42140 B -> 5 CTAs/SM

    float* s_in = (float*)s_rs;   // [INW][INP] = 5624 B, dead after stage 2

    const int X0   = blockIdx.x * TILE;
    const int Y0   = blockIdx.y * TILE;
    const int tid  = threadIdx.x;
    const int lane = tid & 31;
    const int wrow = tid >> 5;    // 0..7

    const bool interior =
        blockIdx.x >= 1 && blockIdx.x <= 126 &&
        blockIdx.y >= 1 && blockIdx.y <= 126;

    // ---- Stage 1: load input tile (origin Y0-3, X0-3) ----
    if (interior) {
        const float* src = x + (size_t)(Y0 - 3) * IMG_W + (X0 - 3);
        #pragma unroll
        for (int it = 0; it < 5; ++it) {
            int r = wrow + 8 * it;
            if (r < INW) {
                const float* row = src + (size_t)r * IMG_W;
                s_in[r * INP + lane] = row[lane];
                if (lane < INW - 32)
                    s_in[r * INP + 32 + lane] = row[32 + lane];
            }
        }
    } else {
        #pragma unroll
        for (int it = 0; it < 5; ++it) {
            int r = wrow + 8 * it;
            if (r < INW) {
                int  gy    = Y0 - 3 + r;
                bool rowok = (gy >= 0) && (gy < IMG_H);
                int  gx    = X0 - 3 + lane;
                float v = 0.0f;
                if (rowok && gx >= 0 && gx < IMG_W)
                    v = x[(size_t)gy * IMG_W + gx];
                s_in[r * INP + lane] = v;
                if (lane < INW - 32) {
                    int gx2 = gx + 32;
                    float v2 = 0.0f;
                    if (rowok && gx2 >= 0 && gx2 < IMG_W)
                        v2 = x[(size_t)gy * IMG_W + gx2];
                    s_in[r * INP + 32 + lane] = v2;
                }
            }
        }
    }
    __syncthreads();

    // ---- Stage 2: column-sliding Sobel + argmax bin + magnitude ----
    // 35 columns x 7 strips of 5 rows = 245 segments; rolling row stats.
    if (tid < 245) {
        int col   = tid % 35;
        int strip = tid / 35;
        int h0    = strip * 5;
        const float* base = s_in + h0 * INP + col;

        float c0 = base[0],       c1 = base[1],       c2 = base[2];
        float d0 = c2 - c0;
        float s0 = fmaf(2.0f, c1, c0) + c2;
        c0 = base[INP]; c1 = base[INP + 1]; c2 = base[INP + 2];
        float d1 = c2 - c0;
        float s1 = fmaf(2.0f, c1, c0) + c2;

        const int  gx    = X0 - 2 + col;
        const bool colok = (gx >= 0) && (gx < IMG_W);

        #pragma unroll
        for (int r = 0; r < 5; ++r) {
            const float* rb = base + (r + 2) * INP;
            c0 = rb[0]; c1 = rb[1]; c2 = rb[2];
            float d2 = c2 - c0;
            float s2 = fmaf(2.0f, c1, c0) + c2;

            float dx = fmaf(2.0f, d1, d0) + d2;
            float dy = s2 - s0;

            float cdx = CC * dx, sdx = SS * dx;
            float cdy = CC * dy, sdy = SS * dy;
            float p  = cdx + sdy;
            float q  = sdx + cdy;
            float r2 = cdy - sdx;
            float t2 = sdy - cdx;

            float bv = p; int bi = 0;
            if ( q  > bv) { bv =  q;  bi = 1; }
            if ( r2 > bv) { bv =  r2; bi = 2; }
            if ( t2 > bv) { bv =  t2; bi = 3; }
            if (-p  > bv) { bv = -p;  bi = 4; }
            if (-q  > bv) { bv = -q;  bi = 5; }
            if (-r2 > bv) { bv = -r2; bi = 6; }
            if (-t2 > bv) { bv = -t2; bi = 7; }

            float mag = sqrtf(fmaf(dx, dx, dy * dy));
            unsigned int bits =
                (__float_as_uint(mag) & 0xFFFFFFF8u) | (unsigned int)bi;

            if (!interior) {
                int gy = Y0 - 2 + h0 + r;
                if (!(colok && gy >= 0 && gy < IMG_H)) bits = 0u;
            }
            s_pk[h0 + r][col] = bits;

            d0 = d1; d1 = d2;
            s0 = s1; s1 = s2;
        }
    }
    __syncthreads();

    // ---- Stage 3: horizontal 4-tap sliding window with one-hot scatter ----
    // Each work item: 4 adjacent rs entries in one row. 35 rows x 8 chunks = 280.
    #pragma unroll
    for (int it = 0; it < 2; ++it) {
        int e = tid + 256 * it;
        if (e < HIST * 8) {
            int h  = e >> 3;
            int x0 = (e & 7) << 2;
            const unsigned int* row = &s_pk[h][x0];

            unsigned int u0 = row[0], u1 = row[1], u2 = row[2], u3 = row[3];
            unsigned int u4 = row[4], u5 = row[5], u6 = row[6];

            float a0 = 0.f, a1 = 0.f, a2 = 0.f, a3 = 0.f;
            float a4 = 0.f, a5 = 0.f, a6 = 0.f, a7 = 0.f;

            #define OH_ADD(U) do {                                  \
                unsigned int _i = (U) & 7u;                          \
                float _m = __uint_as_float(U);                       \
                if (_i == 0u) a0 += _m;  if (_i == 1u) a1 += _m;     \
                if (_i == 2u) a2 += _m;  if (_i == 3u) a3 += _m;     \
                if (_i == 4u) a4 += _m;  if (_i == 5u) a5 += _m;     \
                if (_i == 6u) a6 += _m;  if (_i == 7u) a7 += _m;     \
            } while (0)
            #define OH_SUB(U) do {                                  \
                unsigned int _i = (U) & 7u;                          \
                float _m = __uint_as_float(U);                       \
                if (_i == 0u) a0 -= _m;  if (_i == 1u) a1 -= _m;     \
                if (_i == 2u) a2 -= _m;  if (_i == 3u) a3 -= _m;     \
                if (_i == 4u) a4 -= _m;  if (_i == 5u) a5 -= _m;     \
                if (_i == 6u) a6 -= _m;  if (_i == 7u) a7 -= _m;     \
            } while (0)

            OH_ADD(u0); OH_ADD(u1); OH_ADD(u2); OH_ADD(u3);
            s_rs[0][h][x0] = make_float4(a0, a1, a2, a3);
            s_rs[1][h][x0] = make_float4(a4, a5, a6, a7);

            OH_SUB(u0); OH_ADD(u4);
            s_rs[0][h][x0 + 1] = make_float4(a0, a1, a2, a3);
            s_rs[1][h][x0 + 1] = make_float4(a4, a5, a6, a7);

            OH_SUB(u1); OH_ADD(u5);
            s_rs[0][h][x0 + 2] = make_float4(a0, a1, a2, a3);
            s_rs[1][h][x0 + 2] = make_float4(a4, a5, a6, a7);

            OH_SUB(u2); OH_ADD(u6);
            s_rs[0][h][x0 + 3] = make_float4(a0, a1, a2, a3);
            s_rs[1][h][x0 + 3] = make_float4(a4, a5, a6, a7);

            #undef OH_ADD
            #undef OH_SUB
        }
    }
    __syncthreads();

    // ---- Stage 4: vertical 4-tap sliding sum + store 8 channels ----
    const int    gx    = X0 + lane;
    const size_t plane = (size_t)OUT_H * OUT_W;
    const int    oy0   = wrow * 4;          // 4 consecutive rows per thread

    float4 lo = f4add(f4add(s_rs[0][oy0][lane],     s_rs[0][oy0 + 1][lane]),
                      f4add(s_rs[0][oy0 + 2][lane], s_rs[0][oy0 + 3][lane]));
    float4 hi = f4add(f4add(s_rs[1][oy0][lane],     s_rs[1][oy0 + 1][lane]),
                      f4add(s_rs[1][oy0 + 2][lane], s_rs[1][oy0 + 3][lane]));

    #pragma unroll
    for (int r = 0; r < 4; r++) {
        if (r > 0) {
            lo = f4addsub(lo, s_rs[0][oy0 + r + 3][lane], s_rs[0][oy0 + r - 1][lane]);
            hi = f4addsub(hi, s_rs[1][oy0 + r + 3][lane], s_rs[1][oy0 + r - 1][lane]);
        }
        int gy = Y0 + oy0 + r;
        if (gy < OUT_H && gx < OUT_W) {
            size_t base = (size_t)gy * OUT_W + gx;
            out[0 * plane + base] = lo.x;
            out[1 * plane + base] = lo.y;
            out[2 * plane + base] = lo.z;
            out[3 * plane + base] = lo.w;
            out[4 * plane + base] = hi.x;
            out[5 * plane + base] = hi.y;
            out[6 * plane + base] = hi.z;
            out[7 * plane + base] = hi.w;
        }
    }
}

extern "C" void kernel_launch(void* const* d_in, const int* in_sizes, int n_in,
                              void* d_out, int out_size)
{
    const float* x   = (const float*)d_in[0];
    float*       out = (float*)d_out;
    dim3 grid((OUT_W + TILE - 1) / TILE, (OUT_H + TILE - 1) / TILE);  // 129 x 129
    sift_fused_kernel<<<grid, 256>>>(x, out);
}